// round 7
// baseline (speedup 1.0000x reference)
#include <cuda_runtime.h>
#include <cuda_bf16.h>
#include <cstdint>

// Problem constants
#define Bb 4
#define Nn 16384
#define Cc 128
#define Mm 1024
#define Kk 32
#define COLSX (Bb*Mm*Kk)          // 131072
#define R2c 0.16f
#define XK 160                     // padded input-channel dim for GEMM1 (131 -> 160)
#define NBLK 1024                  // column tiles per GEMM (COLSX/128)

// -------------------- scratch (__device__ globals; no allocations) ---------
__device__ float  g_featT[(size_t)Bb*Nn*Cc];       // (B,N,C)
__device__ float4 g_xyz4[(size_t)Bb*Nn];           // packed xyz
__device__ float  g_newxyz[Bb*Mm*3];
__device__ int    g_idx[Bb*Mm*Kk];
__device__ float  g_W1p[128*XK];                   // [cout][160] permuted: feat|xyz|pad
__device__ float  g_Y1[(size_t)COLSX*128];         // [col][cout]
__device__ float  g_Y2[(size_t)COLSX*128];
__device__ float2 g_mm[(size_t)Bb*Mm*256];         // [bm][cout] (max,min) over K
__device__ float2 g_part[(size_t)256*NBLK];
__device__ float2 g_aff[256];

// -------------------- helpers ----------------------------------------------
__device__ __forceinline__ uint32_t smem_u32(const void* p){
    uint32_t a;
    asm("{ .reg .u64 t; cvta.to.shared.u64 t, %1; cvt.u32.u64 %0, t; }" : "=r"(a) : "l"(p));
    return a;
}
__device__ __forceinline__ void ldm4(uint32_t* r, uint32_t addr){
    asm volatile("ldmatrix.sync.aligned.m8n8.x4.shared.b16 {%0,%1,%2,%3}, [%4];"
        : "=r"(r[0]), "=r"(r[1]), "=r"(r[2]), "=r"(r[3]) : "r"(addr));
}
__device__ __forceinline__ void mma_bf16(float* d, const uint32_t* a, const uint32_t* b){
    asm volatile("mma.sync.aligned.m16n8k16.row.col.f32.bf16.bf16.f32 "
        "{%0,%1,%2,%3}, {%4,%5,%6,%7}, {%8,%9}, {%0,%1,%2,%3};"
        : "+f"(d[0]), "+f"(d[1]), "+f"(d[2]), "+f"(d[3])
        : "r"(a[0]), "r"(a[1]), "r"(a[2]), "r"(a[3]), "r"(b[0]), "r"(b[1]));
}
// split 8 floats into hi/lo bf16 quads
__device__ __forceinline__ void cvt8(const float* f, uint4& H, uint4& L){
    uint32_t hh[4], ll[4];
    #pragma unroll
    for (int i = 0; i < 4; i++){
        __nv_bfloat162 h = __floats2bfloat162_rn(f[2*i], f[2*i+1]);
        float r0 = f[2*i]   - __low2float(h);
        float r1 = f[2*i+1] - __high2float(h);
        __nv_bfloat162 l = __floats2bfloat162_rn(r0, r1);
        hh[i] = *(uint32_t*)&h;
        ll[i] = *(uint32_t*)&l;
    }
    H = make_uint4(hh[0], hh[1], hh[2], hh[3]);
    L = make_uint4(ll[0], ll[1], ll[2], ll[3]);
}

// -------------------- 1. transpose features (B,C,N)->(B,N,C) ---------------
__global__ void transpose_kernel(const float* __restrict__ f){
    __shared__ float tile[32][33];
    const int b  = blockIdx.z;
    const int c0 = blockIdx.y << 5;
    const int n0 = blockIdx.x << 5;
    const int tx = threadIdx.x, ty = threadIdx.y;
    #pragma unroll
    for (int j = 0; j < 32; j += 8)
        tile[ty + j][tx] = f[((size_t)(b*Cc + c0 + ty + j))*Nn + n0 + tx];
    __syncthreads();
    #pragma unroll
    for (int j = 0; j < 32; j += 8)
        g_featT[((size_t)(b*Nn + n0 + ty + j))*Cc + c0 + tx] = tile[tx][ty + j];
}

// -------------------- 2. small prep: xyz4 + W1 prep + newxyz ---------------
__global__ void small_prep_kernel(const float* __restrict__ xyz,
                                  const int* __restrict__ indices,
                                  const float* __restrict__ w1,
                                  float* __restrict__ out){
    int t = blockIdx.x*256 + threadIdx.x;
    if (t < Bb*Nn){
        float4 v; v.x = xyz[t*3+0]; v.y = xyz[t*3+1]; v.z = xyz[t*3+2]; v.w = 0.f;
        g_xyz4[t] = v;
    }
    if (t < 128*XK){
        int o = t / XK, k = t % XK;
        float v = 0.f;
        if (k < 128)       v = w1[o*131 + 3 + k];
        else if (k < 131)  v = w1[o*131 + (k - 128)];
        g_W1p[t] = v;
    }
    if (t < Bb*Mm){
        int i = indices[t];
        const float* p = xyz + ((size_t)(t >> 10)*Nn + i)*3;
        float x = p[0], y = p[1], z = p[2];
        g_newxyz[t*3+0] = x; g_newxyz[t*3+1] = y; g_newxyz[t*3+2] = z;
        out[t*3+0] = x; out[t*3+1] = y; out[t*3+2] = z;
    }
}

// -------------------- 3. ball query: 8 warps/query + ordered merge ---------
__global__ __launch_bounds__(256) void ballquery_kernel(){
    const int q = blockIdx.x;
    const int b = q >> 10;
    const int warp = threadIdx.x >> 5;
    const int lane = threadIdx.x & 31;
    __shared__ int cand[8][33];
    __shared__ int cnts[8];

    const float qx = g_newxyz[q*3+0];
    const float qy = g_newxyz[q*3+1];
    const float qz = g_newxyz[q*3+2];
    const float4* bp = g_xyz4 + (size_t)b*Nn;
    const int seg0 = warp << 11;

    int cnt = 0;
    for (int base = 0; base < 2048; base += 32){
        int n = seg0 + base + lane;
        float4 p = __ldg(bp + n);
        float dx = __fadd_rn(qx, -p.x), dy = __fadd_rn(qy, -p.y), dz = __fadd_rn(qz, -p.z);
        float d2 = __fadd_rn(__fadd_rn(__fmul_rn(dx,dx), __fmul_rn(dy,dy)), __fmul_rn(dz,dz));
        bool w = d2 < R2c;
        unsigned mask = __ballot_sync(0xffffffffu, w);
        int pre = __popc(mask & ((1u << lane) - 1u));
        if (w && cnt + pre < Kk) cand[warp][cnt + pre] = n;
        cnt += __popc(mask);
        if (cnt >= Kk) break;
    }
    if (lane == 0) cnts[warp] = cnt < Kk ? cnt : Kk;
    __syncthreads();

    if (warp == 0){
        int acc = 0, sel = -1, off = 0, first = -1;
        #pragma unroll
        for (int s = 0; s < 8; s++){
            int cs = cnts[s];
            if (sel < 0 && lane < acc + cs){ sel = s; off = lane - acc; }
            if (first < 0 && cs > 0) first = s;
            acc += cs;
        }
        int v = (sel >= 0) ? cand[sel][off]
                           : (first >= 0 ? cand[first][0] : 0);
        g_idx[q*Kk + lane] = v;
    }
}

// -------------------- 4. mma.sync bf16-split GEMM --------------------------
// C[128 m(cout)][128 n(cols)] = A[128,K]*B[128,K]^T.
// B operand LDGs are register-prefetched before the compute phase.
#define OFF_AFF  0
#define OFF_PART 1024
#define OFF_IDX  3072
#define OFF_XYZ  4096
#define OFF_SA   8192
#define OFF_SB   (8192 + 2*16384)
#define OFF_C    8192
#define CPITCH   132
#define SMEM_GEMM (8192 + 128*CPITCH*4)   // 75776

template<int KA, int NC, int KSOUT, bool ACT, bool GATHER, bool FINAL>
__global__ __launch_bounds__(256, 2)
void mma_gemm(const float* __restrict__ Asrc, const float* __restrict__ Bsrc,
              const float* __restrict__ bias, float* __restrict__ Y)
{
    extern __shared__ char smem[];
    const uint32_t sb = smem_u32(smem);
    const int tid = threadIdx.x, wid = tid >> 5, lane = tid & 31;
    const int cb = blockIdx.x << 7;
    const int rb = blockIdx.y << 7;
    const int m0 = (wid >> 1) << 5;
    const int n0w = (wid & 1) << 6;

    float* afs   = (float*)(smem + OFF_AFF);
    int*   sidx  = (int*)(smem + OFF_IDX);
    float4* sxyz = (float4*)(smem + OFF_XYZ);
    const size_t bBase = (size_t)(cb >> 15)*Nn;

    if (ACT && tid < 128) ((float2*)afs)[tid] = g_aff[tid];
    if (GATHER && tid < 128){
        int i = g_idx[cb + tid];
        sidx[tid] = i;
        float4 p = g_xyz4[bBase + i];
        const int bm = (cb + tid) >> 5;
        const float* q = g_newxyz + (size_t)bm*3;
        float4 r; r.x = p.x - q[0]; r.y = p.y - q[1]; r.z = p.z - q[2]; r.w = 0.f;
        sxyz[tid] = r;
    }
    if (ACT || GATHER) __syncthreads();

    float acc[2][8][4];
    #pragma unroll
    for (int a = 0; a < 2; a++)
        #pragma unroll
        for (int b2 = 0; b2 < 8; b2++)
            #pragma unroll
            for (int c = 0; c < 4; c++) acc[a][b2][c] = 0.f;

    float fB[2][8];                                 // prefetched B chunk

    auto PREF_B = [&](int c){
        if (GATHER && c == 4) return;               // xyz chunk: from smem
        const int k0 = c*32;
        #pragma unroll
        for (int it = 0; it < 2; it++){
            const int s = tid + it*256;
            const int n = s >> 2, oct = s & 3;
            const float* src = GATHER
                ? g_featT + ((bBase + (size_t)sidx[n]) << 7) + k0 + oct*8
                : Bsrc + (size_t)(cb + n)*KA + k0 + oct*8;
            *(float4*)&fB[it][0] = __ldg((const float4*)src);
            *(float4*)&fB[it][4] = __ldg((const float4*)(src + 4));
        }
    };
    auto CVST_A = [&](int c){
        const int k0 = c*32;
        char* SAb = smem + OFF_SA + ((c & 1) << 14);
        #pragma unroll
        for (int it = 0; it < 2; it++){
            const int s = tid + it*256;
            const int m = s >> 2, oct = s & 3;
            const float* src = Asrc + (size_t)(rb + m)*KA + k0 + oct*8;
            float f[8];
            *(float4*)&f[0] = __ldg((const float4*)src);
            *(float4*)&f[4] = __ldg((const float4*)(src + 4));
            uint4 H, L; cvt8(f, H, L);
            const uint32_t ro = (uint32_t)m << 7;
            *(uint4*)(SAb + ro + (uint32_t)((oct       ^ (m & 7)) << 4)) = H;
            *(uint4*)(SAb + ro + (uint32_t)(((oct + 4) ^ (m & 7)) << 4)) = L;
        }
    };
    auto CVST_B = [&](int c){
        const int k0 = c*32;
        char* SBb = smem + OFF_SB + ((c & 1) << 14);
        #pragma unroll
        for (int it = 0; it < 2; it++){
            const int s = tid + it*256;
            const int n = s >> 2, oct = s & 3;
            float f[8];
            if (GATHER && c == 4){
                #pragma unroll
                for (int i = 0; i < 8; i++) f[i] = 0.f;
                if (oct == 0){ float4 xr = sxyz[n]; f[0] = xr.x; f[1] = xr.y; f[2] = xr.z; }
            } else {
                #pragma unroll
                for (int i = 0; i < 8; i++) f[i] = fB[it][i];
                if (ACT){
                    #pragma unroll
                    for (int i = 0; i < 8; i++){
                        const int k = k0 + oct*8 + i;
                        f[i] = fmaxf(fmaf(afs[2*k], f[i], afs[2*k+1]), 0.f);
                    }
                }
            }
            uint4 H, L; cvt8(f, H, L);
            const uint32_t ro = (uint32_t)n << 7;
            *(uint4*)(SBb + ro + (uint32_t)((oct       ^ (n & 7)) << 4)) = H;
            *(uint4*)(SBb + ro + (uint32_t)(((oct + 4) ^ (n & 7)) << 4)) = L;
        }
    };

    PREF_B(0);
    CVST_A(0);
    CVST_B(0);
    __syncthreads();

    const int arow = m0 + (lane & 15);
    const int asel = lane >> 4;
    const int nrow0 = n0w + ((lane >> 4) << 3) + (lane & 7);
    const int bsel = (lane >> 3) & 1;

    #pragma unroll 1
    for (int c = 0; c < NC; ++c){
        if (c + 1 < NC) PREF_B(c + 1);              // LDGs in flight during compute
        const uint32_t sbA = sb + OFF_SA + ((c & 1) << 14);
        const uint32_t sbB = sb + OFF_SB + ((c & 1) << 14);
        #pragma unroll
        for (int t = 0; t < 2; t++){
            uint32_t ah[2][4], al[2][4];
            #pragma unroll
            for (int mi = 0; mi < 2; mi++){
                const int row = arow + mi*16;
                const uint32_t base = sbA + ((uint32_t)row << 7);
                const int ch = 2*t + asel;
                ldm4(ah[mi], base + (uint32_t)(((ch    ) ^ (row & 7)) << 4));
                ldm4(al[mi], base + (uint32_t)(((ch + 4) ^ (row & 7)) << 4));
            }
            #pragma unroll
            for (int j = 0; j < 4; j++){
                const int n = nrow0 + j*16;
                const uint32_t nb = sbB + ((uint32_t)n << 7);
                const int ch = 2*t + bsel;
                uint32_t bh[4], bl[4];
                ldm4(bh, nb + (uint32_t)(((ch    ) ^ (n & 7)) << 4));
                mma_bf16(acc[0][2*j],   ah[0], bh + 0);
                mma_bf16(acc[0][2*j+1], ah[0], bh + 2);
                mma_bf16(acc[1][2*j],   ah[1], bh + 0);
                mma_bf16(acc[1][2*j+1], ah[1], bh + 2);
                mma_bf16(acc[0][2*j],   al[0], bh + 0);
                mma_bf16(acc[0][2*j+1], al[0], bh + 2);
                mma_bf16(acc[1][2*j],   al[1], bh + 0);
                mma_bf16(acc[1][2*j+1], al[1], bh + 2);
                ldm4(bl, nb + (uint32_t)(((ch + 4) ^ (n & 7)) << 4));
                mma_bf16(acc[0][2*j],   ah[0], bl + 0);
                mma_bf16(acc[0][2*j+1], ah[0], bl + 2);
                mma_bf16(acc[1][2*j],   ah[1], bl + 0);
                mma_bf16(acc[1][2*j+1], ah[1], bl + 2);
            }
        }
        if (c + 1 < NC){ CVST_A(c + 1); CVST_B(c + 1); }
        __syncthreads();
    }

    // ---------------- epilogue: bias + BN partials + store/reduce ----------
    float* C = (float*)(smem + OFF_C);
    float2* P = (float2*)(smem + OFF_PART);
    const int l4 = lane >> 2, lc = (lane & 3) << 1;
    float sr[4] = {0,0,0,0}, s2r[4] = {0,0,0,0};
    #pragma unroll
    for (int mi = 0; mi < 2; mi++){
        const int r0 = m0 + mi*16 + l4;
        const float bv0 = bias[rb + r0];
        const float bv1 = bias[rb + r0 + 8];
        #pragma unroll
        for (int ni = 0; ni < 8; ni++){
            const int n = n0w + ni*8 + lc;
            float v0 = acc[mi][ni][0] + bv0, v1 = acc[mi][ni][1] + bv0;
            float v2 = acc[mi][ni][2] + bv1, v3 = acc[mi][ni][3] + bv1;
            *(float2*)&C[(size_t)r0*CPITCH + n]       = make_float2(v0, v1);
            *(float2*)&C[(size_t)(r0+8)*CPITCH + n]   = make_float2(v2, v3);
            sr[2*mi]   += v0 + v1;  s2r[2*mi]   += v0*v0 + v1*v1;
            sr[2*mi+1] += v2 + v3;  s2r[2*mi+1] += v2*v2 + v3*v3;
        }
    }
    #pragma unroll
    for (int o = 1; o <= 2; o <<= 1){
        #pragma unroll
        for (int i = 0; i < 4; i++){
            sr[i]  += __shfl_xor_sync(0xffffffffu, sr[i],  o);
            s2r[i] += __shfl_xor_sync(0xffffffffu, s2r[i], o);
        }
    }
    if ((lane & 3) == 0){
        P[wid*32 + l4]      = make_float2(sr[0], s2r[0]);
        P[wid*32 + l4 + 8]  = make_float2(sr[1], s2r[1]);
        P[wid*32 + l4 + 16] = make_float2(sr[2], s2r[2]);
        P[wid*32 + l4 + 24] = make_float2(sr[3], s2r[3]);
    }
    __syncthreads();
    if (tid < 128){
        const int m = tid, lr = m & 31, w0 = (m >> 5) << 1;
        float2 p0 = P[w0*32 + lr], p1 = P[(w0+1)*32 + lr];
        g_part[(size_t)(rb + m)*NBLK + blockIdx.x] = make_float2(p0.x + p1.x, p0.y + p1.y);
    }
    if (FINAL){
        const int row = tid >> 1;
        #pragma unroll
        for (int gg = 0; gg < 2; gg++){
            const int g = ((tid & 1) << 1) + gg;
            const float* src = C + (size_t)row*CPITCH + g*32;
            float mx = -3.4e38f, mn = 3.4e38f;
            #pragma unroll
            for (int k = 0; k < 32; k++){
                float v = src[k];
                mx = fmaxf(mx, v); mn = fminf(mn, v);
            }
            g_mm[(size_t)((cb >> 5) + g)*256 + rb + row] = make_float2(mx, mn);
        }
    } else {
        const int n = tid >> 1, hf = tid & 1;
        float* dst = Y + (size_t)(cb + n)*KSOUT + rb + hf*64;
        #pragma unroll
        for (int i = 0; i < 16; i++){
            float4 v;
            v.x = C[(size_t)(hf*64 + i*4 + 0)*CPITCH + n];
            v.y = C[(size_t)(hf*64 + i*4 + 1)*CPITCH + n];
            v.z = C[(size_t)(hf*64 + i*4 + 2)*CPITCH + n];
            v.w = C[(size_t)(hf*64 + i*4 + 3)*CPITCH + n];
            ((float4*)dst)[i] = v;
        }
    }
}

// -------------------- 5. finalize BN affine --------------------------------
__global__ void finalize_kernel(const float* __restrict__ gamma, const float* __restrict__ beta){
    const int c = blockIdx.x;
    float s = 0.f, s2 = 0.f;
    for (int i = threadIdx.x; i < NBLK; i += 256){
        float2 v = g_part[(size_t)c*NBLK + i];
        s += v.x; s2 += v.y;
    }
    #pragma unroll
    for (int o = 16; o > 0; o >>= 1){
        s  += __shfl_down_sync(0xffffffffu, s,  o);
        s2 += __shfl_down_sync(0xffffffffu, s2, o);
    }
    __shared__ float rs[8], rs2[8];
    int w = threadIdx.x >> 5, l = threadIdx.x & 31;
    if (l == 0){ rs[w] = s; rs2[w] = s2; }
    __syncthreads();
    if (threadIdx.x == 0){
        float S = 0.f, S2 = 0.f;
        #pragma unroll
        for (int i = 0; i < 8; i++){ S += rs[i]; S2 += rs2[i]; }
        float inv = 1.f/(float)COLSX;
        float mu  = S*inv;
        float var = fmaxf(S2*inv - mu*mu, 0.f);
        float a = gamma[c]*rsqrtf(var + 1e-5f);
        g_aff[c] = make_float2(a, beta[c] - a*mu);
    }
}

// -------------------- 6. final: affine + relu on (max|min) -----------------
__global__ __launch_bounds__(256) void finalmax_kernel(float* __restrict__ out){
    const int bm = blockIdx.x;
    const int b = bm >> 10, m = bm & 1023;
    const int co = threadIdx.x;
    const float2 af = g_aff[co];
    const float2 mm = g_mm[(size_t)bm*256 + co];
    const float v = (af.x >= 0.f) ? mm.x : mm.y;
    out[Bb*Mm*3 + (((size_t)(b*256 + co)) << 10) + m] = fmaxf(fmaf(af.x, v, af.y), 0.f);
}

// -------------------- launch ----------------------------------------------
extern "C" void kernel_launch(void* const* d_in, const int* in_sizes, int n_in,
                              void* d_out, int out_size)
{
    const float* points_xyz = (const float*)d_in[0];
    const float* features   = (const float*)d_in[1];
    const int*   indices    = (const int*)  d_in[2];
    const float* w1 = (const float*)d_in[3];
    const float* b1 = (const float*)d_in[4];
    const float* g1 = (const float*)d_in[5];
    const float* be1= (const float*)d_in[6];
    const float* w2 = (const float*)d_in[7];
    const float* b2 = (const float*)d_in[8];
    const float* g2 = (const float*)d_in[9];
    const float* be2= (const float*)d_in[10];
    const float* w3 = (const float*)d_in[11];
    const float* b3 = (const float*)d_in[12];
    const float* g3 = (const float*)d_in[13];
    const float* be3= (const float*)d_in[14];
    float* out = (float*)d_out;

    float *W1p, *Y1, *Y2;
    cudaGetSymbolAddress((void**)&W1p, g_W1p);
    cudaGetSymbolAddress((void**)&Y1,  g_Y1);
    cudaGetSymbolAddress((void**)&Y2,  g_Y2);

    cudaFuncSetAttribute(mma_gemm<XK,  5, 128, false, true,  false>, cudaFuncAttributeMaxDynamicSharedMemorySize, SMEM_GEMM);
    cudaFuncSetAttribute(mma_gemm<128, 4, 128, true,  false, false>, cudaFuncAttributeMaxDynamicSharedMemorySize, SMEM_GEMM);
    cudaFuncSetAttribute(mma_gemm<128, 4, 256, true,  false, true >, cudaFuncAttributeMaxDynamicSharedMemorySize, SMEM_GEMM);

    // prep (2 launches)
    transpose_kernel<<<dim3(Nn/32, Cc/32, Bb), dim3(32,8)>>>(features);
    small_prep_kernel<<<(Bb*Nn + 255)/256, 256>>>(points_xyz, indices, w1, out);

    // ball query
    ballquery_kernel<<<Bb*Mm, 256>>>();

    // layer 1 (gather fused)  -- launch index 3 (ncu -s5 window target)
    mma_gemm<XK, 5, 128, false, true, false><<<dim3(NBLK, 1), 256, SMEM_GEMM>>>(W1p, nullptr, b1, Y1);
    finalize_kernel<<<128, 256>>>(g1, be1);

    // layer 2
    mma_gemm<128, 4, 128, true, false, false><<<dim3(NBLK, 1), 256, SMEM_GEMM>>>(w2, Y1, b2, Y2);
    finalize_kernel<<<128, 256>>>(g2, be2);

    // layer 3 (K-max/min fused)
    mma_gemm<128, 4, 256, true, false, true><<<dim3(NBLK, 2), 256, SMEM_GEMM>>>(w3, Y2, b3, nullptr);
    finalize_kernel<<<256, 256>>>(g3, be3);

    // final: affine + relu on reduced extrema
    finalmax_kernel<<<Bb*Mm, 256>>>(out);

    (void)in_sizes; (void)n_in; (void)out_size;
}

// round 8
// speedup vs baseline: 1.0282x; 1.0282x over previous
#include <cuda_runtime.h>
#include <cuda_bf16.h>
#include <cstdint>

// Problem constants
#define Bb 4
#define Nn 16384
#define Cc 128
#define Mm 1024
#define Kk 32
#define COLSX (Bb*Mm*Kk)          // 131072
#define R2c 0.16f
#define XK 160                     // padded input-channel dim for GEMM1 (131 -> 160)
#define NBLK 1024                  // column tiles per GEMM (COLSX/128)

// -------------------- scratch (__device__ globals; no allocations) ---------
__device__ float  g_featT[(size_t)Bb*Nn*Cc];       // (B,N,C)
__device__ float4 g_xyz4[(size_t)Bb*Nn];           // packed xyz
__device__ float  g_newxyz[Bb*Mm*3];
__device__ int    g_idx[Bb*Mm*Kk];
__device__ float  g_W1p[128*XK];                   // [cout][160] permuted: feat|xyz|pad
__device__ float  g_Y1[(size_t)COLSX*128];         // [col][cout]
__device__ float  g_Y2[(size_t)COLSX*128];
__device__ float2 g_mm[(size_t)Bb*Mm*256];         // [bm][cout] (max,min) over K
__device__ float2 g_part[(size_t)256*NBLK];
__device__ float2 g_aff[256];

// -------------------- helpers ----------------------------------------------
__device__ __forceinline__ uint32_t smem_u32(const void* p){
    uint32_t a;
    asm("{ .reg .u64 t; cvta.to.shared.u64 t, %1; cvt.u32.u64 %0, t; }" : "=r"(a) : "l"(p));
    return a;
}
__device__ __forceinline__ void ldm4(uint32_t* r, uint32_t addr){
    asm volatile("ldmatrix.sync.aligned.m8n8.x4.shared.b16 {%0,%1,%2,%3}, [%4];"
        : "=r"(r[0]), "=r"(r[1]), "=r"(r[2]), "=r"(r[3]) : "r"(addr));
}
__device__ __forceinline__ void mma_bf16(float* d, const uint32_t* a, const uint32_t* b){
    asm volatile("mma.sync.aligned.m16n8k16.row.col.f32.bf16.bf16.f32 "
        "{%0,%1,%2,%3}, {%4,%5,%6,%7}, {%8,%9}, {%0,%1,%2,%3};"
        : "+f"(d[0]), "+f"(d[1]), "+f"(d[2]), "+f"(d[3])
        : "r"(a[0]), "r"(a[1]), "r"(a[2]), "r"(a[3]), "r"(b[0]), "r"(b[1]));
}
// split 8 floats into hi/lo bf16 quads
__device__ __forceinline__ void cvt8(const float* f, uint4& H, uint4& L){
    uint32_t hh[4], ll[4];
    #pragma unroll
    for (int i = 0; i < 4; i++){
        __nv_bfloat162 h = __floats2bfloat162_rn(f[2*i], f[2*i+1]);
        float r0 = f[2*i]   - __low2float(h);
        float r1 = f[2*i+1] - __high2float(h);
        __nv_bfloat162 l = __floats2bfloat162_rn(r0, r1);
        hh[i] = *(uint32_t*)&h;
        ll[i] = *(uint32_t*)&l;
    }
    H = make_uint4(hh[0], hh[1], hh[2], hh[3]);
    L = make_uint4(ll[0], ll[1], ll[2], ll[3]);
}

// -------------------- 1. transpose features (B,C,N)->(B,N,C) ---------------
__global__ void transpose_kernel(const float* __restrict__ f){
    __shared__ float tile[32][33];
    const int b  = blockIdx.z;
    const int c0 = blockIdx.y << 5;
    const int n0 = blockIdx.x << 5;
    const int tx = threadIdx.x, ty = threadIdx.y;
    #pragma unroll
    for (int j = 0; j < 32; j += 8)
        tile[ty + j][tx] = f[((size_t)(b*Cc + c0 + ty + j))*Nn + n0 + tx];
    __syncthreads();
    #pragma unroll
    for (int j = 0; j < 32; j += 8)
        g_featT[((size_t)(b*Nn + n0 + ty + j))*Cc + c0 + tx] = tile[tx][ty + j];
}

// -------------------- 2. small prep: xyz4 + W1 prep + newxyz ---------------
__global__ void small_prep_kernel(const float* __restrict__ xyz,
                                  const int* __restrict__ indices,
                                  const float* __restrict__ w1,
                                  float* __restrict__ out){
    int t = blockIdx.x*256 + threadIdx.x;
    if (t < Bb*Nn){
        float4 v; v.x = xyz[t*3+0]; v.y = xyz[t*3+1]; v.z = xyz[t*3+2]; v.w = 0.f;
        g_xyz4[t] = v;
    }
    if (t < 128*XK){
        int o = t / XK, k = t % XK;
        float v = 0.f;
        if (k < 128)       v = w1[o*131 + 3 + k];
        else if (k < 131)  v = w1[o*131 + (k - 128)];
        g_W1p[t] = v;
    }
    if (t < Bb*Mm){
        int i = indices[t];
        const float* p = xyz + ((size_t)(t >> 10)*Nn + i)*3;
        float x = p[0], y = p[1], z = p[2];
        g_newxyz[t*3+0] = x; g_newxyz[t*3+1] = y; g_newxyz[t*3+2] = z;
        out[t*3+0] = x; out[t*3+1] = y; out[t*3+2] = z;
    }
}

// -------------------- 3. ball query: 8 warps/query + ordered merge ---------
__global__ __launch_bounds__(256) void ballquery_kernel(){
    const int q = blockIdx.x;
    const int b = q >> 10;
    const int warp = threadIdx.x >> 5;
    const int lane = threadIdx.x & 31;
    __shared__ int cand[8][33];
    __shared__ int cnts[8];

    const float qx = g_newxyz[q*3+0];
    const float qy = g_newxyz[q*3+1];
    const float qz = g_newxyz[q*3+2];
    const float4* bp = g_xyz4 + (size_t)b*Nn;
    const int seg0 = warp << 11;

    int cnt = 0;
    for (int base = 0; base < 2048; base += 32){
        int n = seg0 + base + lane;
        float4 p = __ldg(bp + n);
        float dx = __fadd_rn(qx, -p.x), dy = __fadd_rn(qy, -p.y), dz = __fadd_rn(qz, -p.z);
        float d2 = __fadd_rn(__fadd_rn(__fmul_rn(dx,dx), __fmul_rn(dy,dy)), __fmul_rn(dz,dz));
        bool w = d2 < R2c;
        unsigned mask = __ballot_sync(0xffffffffu, w);
        int pre = __popc(mask & ((1u << lane) - 1u));
        if (w && cnt + pre < Kk) cand[warp][cnt + pre] = n;
        cnt += __popc(mask);
        if (cnt >= Kk) break;
    }
    if (lane == 0) cnts[warp] = cnt < Kk ? cnt : Kk;
    __syncthreads();

    if (warp == 0){
        int acc = 0, sel = -1, off = 0, first = -1;
        #pragma unroll
        for (int s = 0; s < 8; s++){
            int cs = cnts[s];
            if (sel < 0 && lane < acc + cs){ sel = s; off = lane - acc; }
            if (first < 0 && cs > 0) first = s;
            acc += cs;
        }
        int v = (sel >= 0) ? cand[sel][off]
                           : (first >= 0 ? cand[first][0] : 0);
        g_idx[q*Kk + lane] = v;
    }
}

// -------------------- 4. mma.sync bf16-split GEMM, 64x64 warp tiles --------
// 4 warps, block tile 128x128, warp tile 64x64 (2m x 2n warp grid).
// C[m(cout)][n(cols)] = A[128,K]*B[128,K]^T.
#define OFF_AFF  0
#define OFF_PART 1024
#define OFF_IDX  3072
#define OFF_XYZ  4096
#define OFF_SA   8192
#define OFF_SB   (8192 + 2*16384)
#define OFF_C    8192
#define CPITCH   132
#define SMEM_GEMM (8192 + 128*CPITCH*4)   // 75776

template<int KA, int NC, int KSOUT, bool ACT, bool GATHER, bool FINAL>
__global__ __launch_bounds__(128, 2)
void mma_gemm(const float* __restrict__ Asrc, const float* __restrict__ Bsrc,
              const float* __restrict__ bias, float* __restrict__ Y)
{
    extern __shared__ char smem[];
    const uint32_t sb = smem_u32(smem);
    const int tid = threadIdx.x, wid = tid >> 5, lane = tid & 31;
    const int cb = blockIdx.x << 7;
    const int rb = blockIdx.y << 7;
    const int m0  = (wid >> 1) << 6;    // warp m-base (64 rows)
    const int n0w = (wid & 1) << 6;     // warp n-base (64 cols)

    float* afs   = (float*)(smem + OFF_AFF);
    int*   sidx  = (int*)(smem + OFF_IDX);
    float4* sxyz = (float4*)(smem + OFF_XYZ);
    const size_t bBase = (size_t)(cb >> 15)*Nn;

    if (ACT) ((float2*)afs)[tid] = g_aff[tid];
    if (GATHER){
        int i = g_idx[cb + tid];
        sidx[tid] = i;
        float4 p = g_xyz4[bBase + i];
        const int bm = (cb + tid) >> 5;
        const float* q = g_newxyz + (size_t)bm*3;
        float4 r; r.x = p.x - q[0]; r.y = p.y - q[1]; r.z = p.z - q[2]; r.w = 0.f;
        sxyz[tid] = r;
    }
    if (ACT || GATHER) __syncthreads();

    float acc[4][8][4];
    #pragma unroll
    for (int a = 0; a < 4; a++)
        #pragma unroll
        for (int b2 = 0; b2 < 8; b2++)
            #pragma unroll
            for (int c = 0; c < 4; c++) acc[a][b2][c] = 0.f;

    float fB[4][8];                                 // prefetched B chunk

    auto PREF_B = [&](int c){
        if (GATHER && c == 4) return;               // xyz chunk: from smem
        const int k0 = c*32;
        #pragma unroll
        for (int it = 0; it < 4; it++){
            const int s = tid + it*128;
            const int n = s >> 2, oct = s & 3;
            const float* src = GATHER
                ? g_featT + ((bBase + (size_t)sidx[n]) << 7) + k0 + oct*8
                : Bsrc + (size_t)(cb + n)*KA + k0 + oct*8;
            *(float4*)&fB[it][0] = __ldg((const float4*)src);
            *(float4*)&fB[it][4] = __ldg((const float4*)(src + 4));
        }
    };
    auto CVST_A = [&](int c){
        const int k0 = c*32;
        char* SAb = smem + OFF_SA + ((c & 1) << 14);
        #pragma unroll
        for (int it = 0; it < 4; it++){
            const int s = tid + it*128;
            const int m = s >> 2, oct = s & 3;
            const float* src = Asrc + (size_t)(rb + m)*KA + k0 + oct*8;
            float f[8];
            *(float4*)&f[0] = __ldg((const float4*)src);
            *(float4*)&f[4] = __ldg((const float4*)(src + 4));
            uint4 H, L; cvt8(f, H, L);
            const uint32_t ro = (uint32_t)m << 7;
            *(uint4*)(SAb + ro + (uint32_t)((oct       ^ (m & 7)) << 4)) = H;
            *(uint4*)(SAb + ro + (uint32_t)(((oct + 4) ^ (m & 7)) << 4)) = L;
        }
    };
    auto CVST_B = [&](int c){
        const int k0 = c*32;
        char* SBb = smem + OFF_SB + ((c & 1) << 14);
        #pragma unroll
        for (int it = 0; it < 4; it++){
            const int s = tid + it*128;
            const int n = s >> 2, oct = s & 3;
            float f[8];
            if (GATHER && c == 4){
                #pragma unroll
                for (int i = 0; i < 8; i++) f[i] = 0.f;
                if (oct == 0){ float4 xr = sxyz[n]; f[0] = xr.x; f[1] = xr.y; f[2] = xr.z; }
            } else {
                #pragma unroll
                for (int i = 0; i < 8; i++) f[i] = fB[it][i];
                if (ACT){
                    #pragma unroll
                    for (int i = 0; i < 8; i++){
                        const int k = k0 + oct*8 + i;
                        f[i] = fmaxf(fmaf(afs[2*k], f[i], afs[2*k+1]), 0.f);
                    }
                }
            }
            uint4 H, L; cvt8(f, H, L);
            const uint32_t ro = (uint32_t)n << 7;
            *(uint4*)(SBb + ro + (uint32_t)((oct       ^ (n & 7)) << 4)) = H;
            *(uint4*)(SBb + ro + (uint32_t)(((oct + 4) ^ (n & 7)) << 4)) = L;
        }
    };

    PREF_B(0);
    CVST_A(0);
    CVST_B(0);
    __syncthreads();

    const int arow = m0 + (lane & 15);
    const int asel = lane >> 4;
    const int nrow0 = n0w + ((lane >> 4) << 3) + (lane & 7);
    const int bsel = (lane >> 3) & 1;

    #pragma unroll 1
    for (int c = 0; c < NC; ++c){
        if (c + 1 < NC) PREF_B(c + 1);
        const uint32_t sbA = sb + OFF_SA + ((c & 1) << 14);
        const uint32_t sbB = sb + OFF_SB + ((c & 1) << 14);
        #pragma unroll
        for (int t = 0; t < 2; t++){
            uint32_t ah[4][4], al[4][4];
            #pragma unroll
            for (int mi = 0; mi < 4; mi++){
                const int row = arow + mi*16;
                const uint32_t base = sbA + ((uint32_t)row << 7);
                const int ch = 2*t + asel;
                ldm4(ah[mi], base + (uint32_t)(((ch    ) ^ (row & 7)) << 4));
                ldm4(al[mi], base + (uint32_t)(((ch + 4) ^ (row & 7)) << 4));
            }
            #pragma unroll
            for (int j = 0; j < 4; j++){
                const int n = nrow0 + j*16;
                const uint32_t nb = sbB + ((uint32_t)n << 7);
                const int ch = 2*t + bsel;
                uint32_t bh[4], bl[4];
                ldm4(bh, nb + (uint32_t)(((ch    ) ^ (n & 7)) << 4));
                #pragma unroll
                for (int mi = 0; mi < 4; mi++){
                    mma_bf16(acc[mi][2*j],   ah[mi], bh + 0);
                    mma_bf16(acc[mi][2*j+1], ah[mi], bh + 2);
                }
                #pragma unroll
                for (int mi = 0; mi < 4; mi++){
                    mma_bf16(acc[mi][2*j],   al[mi], bh + 0);
                    mma_bf16(acc[mi][2*j+1], al[mi], bh + 2);
                }
                ldm4(bl, nb + (uint32_t)(((ch + 4) ^ (n & 7)) << 4));
                #pragma unroll
                for (int mi = 0; mi < 4; mi++){
                    mma_bf16(acc[mi][2*j],   ah[mi], bl + 0);
                    mma_bf16(acc[mi][2*j+1], ah[mi], bl + 2);
                }
            }
        }
        if (c + 1 < NC){ CVST_A(c + 1); CVST_B(c + 1); }
        __syncthreads();
    }

    // ---------------- epilogue: bias + BN partials + store/reduce ----------
    float* C = (float*)(smem + OFF_C);
    float2* P = (float2*)(smem + OFF_PART);   // [4 warps][64 rows]
    const int l4 = lane >> 2, lc = (lane & 3) << 1;
    float sr[8], s2r[8];
    #pragma unroll
    for (int i = 0; i < 8; i++){ sr[i] = 0.f; s2r[i] = 0.f; }
    #pragma unroll
    for (int mi = 0; mi < 4; mi++){
        const int r0 = m0 + mi*16 + l4;
        const float bv0 = bias[rb + r0];
        const float bv1 = bias[rb + r0 + 8];
        #pragma unroll
        for (int ni = 0; ni < 8; ni++){
            const int n = n0w + ni*8 + lc;
            float v0 = acc[mi][ni][0] + bv0, v1 = acc[mi][ni][1] + bv0;
            float v2 = acc[mi][ni][2] + bv1, v3 = acc[mi][ni][3] + bv1;
            *(float2*)&C[(size_t)r0*CPITCH + n]       = make_float2(v0, v1);
            *(float2*)&C[(size_t)(r0+8)*CPITCH + n]   = make_float2(v2, v3);
            sr[2*mi]   += v0 + v1;  s2r[2*mi]   += v0*v0 + v1*v1;
            sr[2*mi+1] += v2 + v3;  s2r[2*mi+1] += v2*v2 + v3*v3;
        }
    }
    #pragma unroll
    for (int o = 1; o <= 2; o <<= 1){
        #pragma unroll
        for (int i = 0; i < 8; i++){
            sr[i]  += __shfl_xor_sync(0xffffffffu, sr[i],  o);
            s2r[i] += __shfl_xor_sync(0xffffffffu, s2r[i], o);
        }
    }
    if ((lane & 3) == 0){
        #pragma unroll
        for (int mi = 0; mi < 4; mi++){
            P[wid*64 + mi*16 + l4]     = make_float2(sr[2*mi],   s2r[2*mi]);
            P[wid*64 + mi*16 + l4 + 8] = make_float2(sr[2*mi+1], s2r[2*mi+1]);
        }
    }
    __syncthreads();
    {
        const int row = tid, wm = row >> 6, lr = row & 63;
        float2 p0 = P[(wm*2 + 0)*64 + lr], p1 = P[(wm*2 + 1)*64 + lr];
        g_part[(size_t)(rb + row)*NBLK + blockIdx.x] = make_float2(p0.x + p1.x, p0.y + p1.y);
    }
    if (FINAL){
        const int row = tid;
        #pragma unroll
        for (int g = 0; g < 4; g++){
            const float* src = C + (size_t)row*CPITCH + g*32;
            float mx = -3.4e38f, mn = 3.4e38f;
            #pragma unroll
            for (int k = 0; k < 32; k++){
                float v = src[k];
                mx = fmaxf(mx, v); mn = fminf(mn, v);
            }
            g_mm[(size_t)((cb >> 5) + g)*256 + rb + row] = make_float2(mx, mn);
        }
    } else {
        const int n = tid;
        float* dst = Y + (size_t)(cb + n)*KSOUT + rb;
        #pragma unroll 8
        for (int i = 0; i < 32; i++){
            float4 v;
            v.x = C[(size_t)(i*4 + 0)*CPITCH + n];
            v.y = C[(size_t)(i*4 + 1)*CPITCH + n];
            v.z = C[(size_t)(i*4 + 2)*CPITCH + n];
            v.w = C[(size_t)(i*4 + 3)*CPITCH + n];
            ((float4*)dst)[i] = v;
        }
    }
}

// -------------------- 5. finalize BN affine --------------------------------
__global__ void finalize_kernel(const float* __restrict__ gamma, const float* __restrict__ beta){
    const int c = blockIdx.x;
    float s = 0.f, s2 = 0.f;
    for (int i = threadIdx.x; i < NBLK; i += 256){
        float2 v = g_part[(size_t)c*NBLK + i];
        s += v.x; s2 += v.y;
    }
    #pragma unroll
    for (int o = 16; o > 0; o >>= 1){
        s  += __shfl_down_sync(0xffffffffu, s,  o);
        s2 += __shfl_down_sync(0xffffffffu, s2, o);
    }
    __shared__ float rs[8], rs2[8];
    int w = threadIdx.x >> 5, l = threadIdx.x & 31;
    if (l == 0){ rs[w] = s; rs2[w] = s2; }
    __syncthreads();
    if (threadIdx.x == 0){
        float S = 0.f, S2 = 0.f;
        #pragma unroll
        for (int i = 0; i < 8; i++){ S += rs[i]; S2 += rs2[i]; }
        float inv = 1.f/(float)COLSX;
        float mu  = S*inv;
        float var = fmaxf(S2*inv - mu*mu, 0.f);
        float a = gamma[c]*rsqrtf(var + 1e-5f);
        g_aff[c] = make_float2(a, beta[c] - a*mu);
    }
}

// -------------------- 6. final: affine + relu on (max|min) -----------------
__global__ __launch_bounds__(256) void finalmax_kernel(float* __restrict__ out){
    const int bm = blockIdx.x;
    const int b = bm >> 10, m = bm & 1023;
    const int co = threadIdx.x;
    const float2 af = g_aff[co];
    const float2 mm = g_mm[(size_t)bm*256 + co];
    const float v = (af.x >= 0.f) ? mm.x : mm.y;
    out[Bb*Mm*3 + (((size_t)(b*256 + co)) << 10) + m] = fmaxf(fmaf(af.x, v, af.y), 0.f);
}

// -------------------- launch ----------------------------------------------
extern "C" void kernel_launch(void* const* d_in, const int* in_sizes, int n_in,
                              void* d_out, int out_size)
{
    const float* points_xyz = (const float*)d_in[0];
    const float* features   = (const float*)d_in[1];
    const int*   indices    = (const int*)  d_in[2];
    const float* w1 = (const float*)d_in[3];
    const float* b1 = (const float*)d_in[4];
    const float* g1 = (const float*)d_in[5];
    const float* be1= (const float*)d_in[6];
    const float* w2 = (const float*)d_in[7];
    const float* b2 = (const float*)d_in[8];
    const float* g2 = (const float*)d_in[9];
    const float* be2= (const float*)d_in[10];
    const float* w3 = (const float*)d_in[11];
    const float* b3 = (const float*)d_in[12];
    const float* g3 = (const float*)d_in[13];
    const float* be3= (const float*)d_in[14];
    float* out = (float*)d_out;

    float *W1p, *Y1, *Y2;
    cudaGetSymbolAddress((void**)&W1p, g_W1p);
    cudaGetSymbolAddress((void**)&Y1,  g_Y1);
    cudaGetSymbolAddress((void**)&Y2,  g_Y2);

    cudaFuncSetAttribute(mma_gemm<XK,  5, 128, false, true,  false>, cudaFuncAttributeMaxDynamicSharedMemorySize, SMEM_GEMM);
    cudaFuncSetAttribute(mma_gemm<128, 4, 128, true,  false, false>, cudaFuncAttributeMaxDynamicSharedMemorySize, SMEM_GEMM);
    cudaFuncSetAttribute(mma_gemm<128, 4, 256, true,  false, true >, cudaFuncAttributeMaxDynamicSharedMemorySize, SMEM_GEMM);

    // prep (2 launches)
    transpose_kernel<<<dim3(Nn/32, Cc/32, Bb), dim3(32,8)>>>(features);
    small_prep_kernel<<<(Bb*Nn + 255)/256, 256>>>(points_xyz, indices, w1, out);

    // ball query
    ballquery_kernel<<<Bb*Mm, 256>>>();

    // layer 1 (gather fused)  -- launch index 3 (ncu -s5 window target)
    mma_gemm<XK, 5, 128, false, true, false><<<dim3(NBLK, 1), 128, SMEM_GEMM>>>(W1p, nullptr, b1, Y1);
    finalize_kernel<<<128, 256>>>(g1, be1);

    // layer 2
    mma_gemm<128, 4, 128, true, false, false><<<dim3(NBLK, 1), 128, SMEM_GEMM>>>(w2, Y1, b2, Y2);
    finalize_kernel<<<128, 256>>>(g2, be2);

    // layer 3 (K-max/min fused)
    mma_gemm<128, 4, 256, true, false, true><<<dim3(NBLK, 2), 128, SMEM_GEMM>>>(w3, Y2, b3, nullptr);
    finalize_kernel<<<256, 256>>>(g3, be3);

    // final: affine + relu on reduced extrema
    finalmax_kernel<<<Bb*Mm, 256>>>(out);

    (void)in_sizes; (void)n_in; (void)out_size;
}

// round 9
// speedup vs baseline: 1.0735x; 1.0440x over previous
#include <cuda_runtime.h>
#include <cuda_bf16.h>
#include <cstdint>

// Problem constants
#define Bb 4
#define Nn 16384
#define Cc 128
#define Mm 1024
#define Kk 32
#define COLSX (Bb*Mm*Kk)          // 131072
#define R2c 0.16f
#define XK 160                     // padded input-channel dim for GEMM1 (131 -> 160)
#define NBLK 1024                  // column tiles per GEMM (COLSX/128)

// -------------------- scratch (__device__ globals; no allocations) ---------
__device__ float  g_featT[(size_t)Bb*Nn*Cc];       // (B,N,C)
__device__ float4 g_xyz4[(size_t)Bb*Nn];           // packed xyz
__device__ float  g_newxyz[Bb*Mm*3];
__device__ int    g_idx[Bb*Mm*Kk];
__device__ float  g_W1p[128*XK];                   // [cout][160] permuted: feat|xyz|pad
__device__ float  g_Y1[(size_t)COLSX*128];         // [col][cout]
__device__ float  g_Y2[(size_t)COLSX*128];
__device__ float2 g_mm[(size_t)Bb*Mm*256];         // [bm][cout] (max,min) over K
__device__ float2 g_part[(size_t)256*NBLK];
__device__ float2 g_aff[256];

// -------------------- helpers ----------------------------------------------
__device__ __forceinline__ uint32_t smem_u32(const void* p){
    uint32_t a;
    asm("{ .reg .u64 t; cvta.to.shared.u64 t, %1; cvt.u32.u64 %0, t; }" : "=r"(a) : "l"(p));
    return a;
}
__device__ __forceinline__ void ldm4(uint32_t* r, uint32_t addr){
    asm volatile("ldmatrix.sync.aligned.m8n8.x4.shared.b16 {%0,%1,%2,%3}, [%4];"
        : "=r"(r[0]), "=r"(r[1]), "=r"(r[2]), "=r"(r[3]) : "r"(addr));
}
__device__ __forceinline__ void mma_bf16(float* d, const uint32_t* a, const uint32_t* b){
    asm volatile("mma.sync.aligned.m16n8k16.row.col.f32.bf16.bf16.f32 "
        "{%0,%1,%2,%3}, {%4,%5,%6,%7}, {%8,%9}, {%0,%1,%2,%3};"
        : "+f"(d[0]), "+f"(d[1]), "+f"(d[2]), "+f"(d[3])
        : "r"(a[0]), "r"(a[1]), "r"(a[2]), "r"(a[3]), "r"(b[0]), "r"(b[1]));
}
// split 8 floats into hi/lo bf16 quads
__device__ __forceinline__ void cvt8(const float* f, uint4& H, uint4& L){
    uint32_t hh[4], ll[4];
    #pragma unroll
    for (int i = 0; i < 4; i++){
        __nv_bfloat162 h = __floats2bfloat162_rn(f[2*i], f[2*i+1]);
        float r0 = f[2*i]   - __low2float(h);
        float r1 = f[2*i+1] - __high2float(h);
        __nv_bfloat162 l = __floats2bfloat162_rn(r0, r1);
        hh[i] = *(uint32_t*)&h;
        ll[i] = *(uint32_t*)&l;
    }
    H = make_uint4(hh[0], hh[1], hh[2], hh[3]);
    L = make_uint4(ll[0], ll[1], ll[2], ll[3]);
}

// -------------------- 1. transpose features (B,C,N)->(B,N,C) ---------------
__global__ void transpose_kernel(const float* __restrict__ f){
    __shared__ float tile[32][33];
    const int b  = blockIdx.z;
    const int c0 = blockIdx.y << 5;
    const int n0 = blockIdx.x << 5;
    const int tx = threadIdx.x, ty = threadIdx.y;
    #pragma unroll
    for (int j = 0; j < 32; j += 8)
        tile[ty + j][tx] = f[((size_t)(b*Cc + c0 + ty + j))*Nn + n0 + tx];
    __syncthreads();
    #pragma unroll
    for (int j = 0; j < 32; j += 8)
        g_featT[((size_t)(b*Nn + n0 + ty + j))*Cc + c0 + tx] = tile[tx][ty + j];
}

// -------------------- 2. small prep: xyz4 + W1 prep + newxyz ---------------
__global__ void small_prep_kernel(const float* __restrict__ xyz,
                                  const int* __restrict__ indices,
                                  const float* __restrict__ w1,
                                  float* __restrict__ out){
    int t = blockIdx.x*256 + threadIdx.x;
    if (t < Bb*Nn){
        float4 v; v.x = xyz[t*3+0]; v.y = xyz[t*3+1]; v.z = xyz[t*3+2]; v.w = 0.f;
        g_xyz4[t] = v;
    }
    if (t < 128*XK){
        int o = t / XK, k = t % XK;
        float v = 0.f;
        if (k < 128)       v = w1[o*131 + 3 + k];
        else if (k < 131)  v = w1[o*131 + (k - 128)];
        g_W1p[t] = v;
    }
    if (t < Bb*Mm){
        int i = indices[t];
        const float* p = xyz + ((size_t)(t >> 10)*Nn + i)*3;
        float x = p[0], y = p[1], z = p[2];
        g_newxyz[t*3+0] = x; g_newxyz[t*3+1] = y; g_newxyz[t*3+2] = z;
        out[t*3+0] = x; out[t*3+1] = y; out[t*3+2] = z;
    }
}

// -------------------- 3. ball query: 16 warps/query + ordered merge --------
__global__ __launch_bounds__(512) void ballquery_kernel(){
    const int q = blockIdx.x;
    const int b = q >> 10;
    const int warp = threadIdx.x >> 5;
    const int lane = threadIdx.x & 31;
    __shared__ int cand[16][33];
    __shared__ int cnts[16];

    const float qx = g_newxyz[q*3+0];
    const float qy = g_newxyz[q*3+1];
    const float qz = g_newxyz[q*3+2];
    const float4* bp = g_xyz4 + (size_t)b*Nn;
    const int seg0 = warp << 10;              // warp*1024

    int cnt = 0;
    for (int base = 0; base < 1024; base += 32){
        int n = seg0 + base + lane;
        float4 p = __ldg(bp + n);
        float dx = __fadd_rn(qx, -p.x), dy = __fadd_rn(qy, -p.y), dz = __fadd_rn(qz, -p.z);
        float d2 = __fadd_rn(__fadd_rn(__fmul_rn(dx,dx), __fmul_rn(dy,dy)), __fmul_rn(dz,dz));
        bool w = d2 < R2c;
        unsigned mask = __ballot_sync(0xffffffffu, w);
        int pre = __popc(mask & ((1u << lane) - 1u));
        if (w && cnt + pre < Kk) cand[warp][cnt + pre] = n;
        cnt += __popc(mask);
        if (cnt >= Kk) break;
    }
    if (lane == 0) cnts[warp] = cnt < Kk ? cnt : Kk;
    __syncthreads();

    if (warp == 0){
        int acc = 0, sel = -1, off = 0, first = -1;
        #pragma unroll
        for (int s = 0; s < 16; s++){
            int cs = cnts[s];
            if (sel < 0 && lane < acc + cs){ sel = s; off = lane - acc; }
            if (first < 0 && cs > 0) first = s;
            acc += cs;
        }
        int v = (sel >= 0) ? cand[sel][off]
                           : (first >= 0 ? cand[first][0] : 0);
        g_idx[q*Kk + lane] = v;
    }
}

// -------------------- 4. mma.sync bf16-split GEMM, 64x64 warp tiles --------
// 4 warps, block tile 128x128, warp tile 64x64.
// ARES: A (weights) converted ONCE into resident smem (per-chunk blocks);
//       mainloop streams only B through a double buffer.
#define OFF_AFF  0
#define OFF_PART 1024
#define OFF_IDX  3072
#define OFF_XYZ  4096
#define OFF_SA   8192
#define OFF_C    8192
#define CPITCH   132

template<int KA, int NC, int KSOUT, bool ACT, bool GATHER, bool FINAL, bool ARES>
__global__ __launch_bounds__(128, 2)
void mma_gemm(const float* __restrict__ Asrc, const float* __restrict__ Bsrc,
              const float* __restrict__ bias, float* __restrict__ Y)
{
    constexpr int OFF_SB = ARES ? (OFF_SA + NC*16384) : (OFF_SA + 2*16384);
    extern __shared__ char smem[];
    const uint32_t sb = smem_u32(smem);
    const int tid = threadIdx.x, wid = tid >> 5, lane = tid & 31;
    const int cb = blockIdx.x << 7;
    const int rb = blockIdx.y << 7;
    const int m0  = (wid >> 1) << 6;    // warp m-base (64 rows)
    const int n0w = (wid & 1) << 6;     // warp n-base (64 cols)

    float* afs   = (float*)(smem + OFF_AFF);
    int*   sidx  = (int*)(smem + OFF_IDX);
    float4* sxyz = (float4*)(smem + OFF_XYZ);
    const size_t bBase = (size_t)(cb >> 15)*Nn;

    if (ACT) ((float2*)afs)[tid] = g_aff[tid];
    if (GATHER){
        int i = g_idx[cb + tid];
        sidx[tid] = i;
        float4 p = g_xyz4[bBase + i];
        const int bm = (cb + tid) >> 5;
        const float* q = g_newxyz + (size_t)bm*3;
        float4 r; r.x = p.x - q[0]; r.y = p.y - q[1]; r.z = p.z - q[2]; r.w = 0.f;
        sxyz[tid] = r;
    }
    if (ACT || GATHER) __syncthreads();

    float acc[4][8][4];
    #pragma unroll
    for (int a = 0; a < 4; a++)
        #pragma unroll
        for (int b2 = 0; b2 < 8; b2++)
            #pragma unroll
            for (int c = 0; c < 4; c++) acc[a][b2][c] = 0.f;

    float fB[4][8];                                 // prefetched B chunk

    auto PREF_B = [&](int c){
        if (GATHER && c == 4) return;               // xyz chunk: from smem
        const int k0 = c*32;
        #pragma unroll
        for (int it = 0; it < 4; it++){
            const int s = tid + it*128;
            const int n = s >> 2, oct = s & 3;
            const float* src = GATHER
                ? g_featT + ((bBase + (size_t)sidx[n]) << 7) + k0 + oct*8
                : Bsrc + (size_t)(cb + n)*KA + k0 + oct*8;
            *(float4*)&fB[it][0] = __ldg((const float4*)src);
            *(float4*)&fB[it][4] = __ldg((const float4*)(src + 4));
        }
    };
    auto CVST_A = [&](int c, char* SAb){
        const int k0 = c*32;
        #pragma unroll
        for (int it = 0; it < 4; it++){
            const int s = tid + it*128;
            const int m = s >> 2, oct = s & 3;
            const float* src = Asrc + (size_t)(rb + m)*KA + k0 + oct*8;
            float f[8];
            *(float4*)&f[0] = __ldg((const float4*)src);
            *(float4*)&f[4] = __ldg((const float4*)(src + 4));
            uint4 H, L; cvt8(f, H, L);
            const uint32_t ro = (uint32_t)m << 7;
            *(uint4*)(SAb + ro + (uint32_t)((oct       ^ (m & 7)) << 4)) = H;
            *(uint4*)(SAb + ro + (uint32_t)(((oct + 4) ^ (m & 7)) << 4)) = L;
        }
    };
    auto CVST_B = [&](int c){
        const int k0 = c*32;
        char* SBb = smem + OFF_SB + ((c & 1) << 14);
        #pragma unroll
        for (int it = 0; it < 4; it++){
            const int s = tid + it*128;
            const int n = s >> 2, oct = s & 3;
            float f[8];
            if (GATHER && c == 4){
                #pragma unroll
                for (int i = 0; i < 8; i++) f[i] = 0.f;
                if (oct == 0){ float4 xr = sxyz[n]; f[0] = xr.x; f[1] = xr.y; f[2] = xr.z; }
            } else {
                #pragma unroll
                for (int i = 0; i < 8; i++) f[i] = fB[it][i];
                if (ACT){
                    #pragma unroll
                    for (int i = 0; i < 8; i++){
                        const int k = k0 + oct*8 + i;
                        f[i] = fmaxf(fmaf(afs[2*k], f[i], afs[2*k+1]), 0.f);
                    }
                }
            }
            uint4 H, L; cvt8(f, H, L);
            const uint32_t ro = (uint32_t)n << 7;
            *(uint4*)(SBb + ro + (uint32_t)((oct       ^ (n & 7)) << 4)) = H;
            *(uint4*)(SBb + ro + (uint32_t)(((oct + 4) ^ (n & 7)) << 4)) = L;
        }
    };

    PREF_B(0);
    if (ARES){
        #pragma unroll
        for (int c = 0; c < NC; c++) CVST_A(c, smem + OFF_SA + c*16384);
    } else {
        CVST_A(0, smem + OFF_SA);
    }
    CVST_B(0);
    __syncthreads();

    const int arow = m0 + (lane & 15);
    const int asel = lane >> 4;
    const int nrow0 = n0w + ((lane >> 4) << 3) + (lane & 7);
    const int bsel = (lane >> 3) & 1;

    #pragma unroll 1
    for (int c = 0; c < NC; ++c){
        if (c + 1 < NC) PREF_B(c + 1);
        const uint32_t sbA = sb + OFF_SA + (ARES ? c*16384 : (c & 1) << 14);
        const uint32_t sbB = sb + OFF_SB + ((c & 1) << 14);
        #pragma unroll
        for (int t = 0; t < 2; t++){
            uint32_t ah[4][4], al[4][4];
            #pragma unroll
            for (int mi = 0; mi < 4; mi++){
                const int row = arow + mi*16;
                const uint32_t base = sbA + ((uint32_t)row << 7);
                const int ch = 2*t + asel;
                ldm4(ah[mi], base + (uint32_t)(((ch    ) ^ (row & 7)) << 4));
                ldm4(al[mi], base + (uint32_t)(((ch + 4) ^ (row & 7)) << 4));
            }
            #pragma unroll
            for (int j = 0; j < 4; j++){
                const int n = nrow0 + j*16;
                const uint32_t nb = sbB + ((uint32_t)n << 7);
                const int ch = 2*t + bsel;
                uint32_t bh[4], bl[4];
                ldm4(bh, nb + (uint32_t)(((ch    ) ^ (n & 7)) << 4));
                #pragma unroll
                for (int mi = 0; mi < 4; mi++){
                    mma_bf16(acc[mi][2*j],   ah[mi], bh + 0);
                    mma_bf16(acc[mi][2*j+1], ah[mi], bh + 2);
                }
                #pragma unroll
                for (int mi = 0; mi < 4; mi++){
                    mma_bf16(acc[mi][2*j],   al[mi], bh + 0);
                    mma_bf16(acc[mi][2*j+1], al[mi], bh + 2);
                }
                ldm4(bl, nb + (uint32_t)(((ch + 4) ^ (n & 7)) << 4));
                #pragma unroll
                for (int mi = 0; mi < 4; mi++){
                    mma_bf16(acc[mi][2*j],   ah[mi], bl + 0);
                    mma_bf16(acc[mi][2*j+1], ah[mi], bl + 2);
                }
            }
        }
        if (c + 1 < NC){
            if (!ARES) CVST_A(c + 1, smem + OFF_SA + (((c + 1) & 1) << 14));
            CVST_B(c + 1);
        }
        __syncthreads();
    }

    // ---------------- epilogue: bias + BN partials + store/reduce ----------
    float* C = (float*)(smem + OFF_C);
    float2* P = (float2*)(smem + OFF_PART);   // [4 warps][64 rows]
    const int l4 = lane >> 2, lc = (lane & 3) << 1;
    float sr[8], s2r[8];
    #pragma unroll
    for (int i = 0; i < 8; i++){ sr[i] = 0.f; s2r[i] = 0.f; }
    #pragma unroll
    for (int mi = 0; mi < 4; mi++){
        const int r0 = m0 + mi*16 + l4;
        const float bv0 = bias[rb + r0];
        const float bv1 = bias[rb + r0 + 8];
        #pragma unroll
        for (int ni = 0; ni < 8; ni++){
            const int n = n0w + ni*8 + lc;
            float v0 = acc[mi][ni][0] + bv0, v1 = acc[mi][ni][1] + bv0;
            float v2 = acc[mi][ni][2] + bv1, v3 = acc[mi][ni][3] + bv1;
            *(float2*)&C[(size_t)r0*CPITCH + n]       = make_float2(v0, v1);
            *(float2*)&C[(size_t)(r0+8)*CPITCH + n]   = make_float2(v2, v3);
            sr[2*mi]   += v0 + v1;  s2r[2*mi]   += v0*v0 + v1*v1;
            sr[2*mi+1] += v2 + v3;  s2r[2*mi+1] += v2*v2 + v3*v3;
        }
    }
    #pragma unroll
    for (int o = 1; o <= 2; o <<= 1){
        #pragma unroll
        for (int i = 0; i < 8; i++){
            sr[i]  += __shfl_xor_sync(0xffffffffu, sr[i],  o);
            s2r[i] += __shfl_xor_sync(0xffffffffu, s2r[i], o);
        }
    }
    if ((lane & 3) == 0){
        #pragma unroll
        for (int mi = 0; mi < 4; mi++){
            P[wid*64 + mi*16 + l4]     = make_float2(sr[2*mi],   s2r[2*mi]);
            P[wid*64 + mi*16 + l4 + 8] = make_float2(sr[2*mi+1], s2r[2*mi+1]);
        }
    }
    __syncthreads();
    {
        const int row = tid, wm = row >> 6, lr = row & 63;
        float2 p0 = P[(wm*2 + 0)*64 + lr], p1 = P[(wm*2 + 1)*64 + lr];
        g_part[(size_t)(rb + row)*NBLK + blockIdx.x] = make_float2(p0.x + p1.x, p0.y + p1.y);
    }
    if (FINAL){
        const int row = tid;
        #pragma unroll
        for (int g = 0; g < 4; g++){
            const float* src = C + (size_t)row*CPITCH + g*32;
            float mx = -3.4e38f, mn = 3.4e38f;
            #pragma unroll
            for (int k = 0; k < 32; k++){
                float v = src[k];
                mx = fmaxf(mx, v); mn = fminf(mn, v);
            }
            g_mm[(size_t)((cb >> 5) + g)*256 + rb + row] = make_float2(mx, mn);
        }
    } else {
        const int n = tid;
        float* dst = Y + (size_t)(cb + n)*KSOUT + rb;
        #pragma unroll 8
        for (int i = 0; i < 32; i++){
            float4 v;
            v.x = C[(size_t)(i*4 + 0)*CPITCH + n];
            v.y = C[(size_t)(i*4 + 1)*CPITCH + n];
            v.z = C[(size_t)(i*4 + 2)*CPITCH + n];
            v.w = C[(size_t)(i*4 + 3)*CPITCH + n];
            ((float4*)dst)[i] = v;
        }
    }
}

// -------------------- 5. finalize BN affine --------------------------------
__global__ void finalize_kernel(const float* __restrict__ gamma, const float* __restrict__ beta){
    const int c = blockIdx.x;
    float s = 0.f, s2 = 0.f;
    for (int i = threadIdx.x; i < NBLK; i += 256){
        float2 v = g_part[(size_t)c*NBLK + i];
        s += v.x; s2 += v.y;
    }
    #pragma unroll
    for (int o = 16; o > 0; o >>= 1){
        s  += __shfl_down_sync(0xffffffffu, s,  o);
        s2 += __shfl_down_sync(0xffffffffu, s2, o);
    }
    __shared__ float rs[8], rs2[8];
    int w = threadIdx.x >> 5, l = threadIdx.x & 31;
    if (l == 0){ rs[w] = s; rs2[w] = s2; }
    __syncthreads();
    if (threadIdx.x == 0){
        float S = 0.f, S2 = 0.f;
        #pragma unroll
        for (int i = 0; i < 8; i++){ S += rs[i]; S2 += rs2[i]; }
        float inv = 1.f/(float)COLSX;
        float mu  = S*inv;
        float var = fmaxf(S2*inv - mu*mu, 0.f);
        float a = gamma[c]*rsqrtf(var + 1e-5f);
        g_aff[c] = make_float2(a, beta[c] - a*mu);
    }
}

// -------------------- 6. final: affine + relu on (max|min) -----------------
__global__ __launch_bounds__(256) void finalmax_kernel(float* __restrict__ out){
    const int bm = blockIdx.x;
    const int b = bm >> 10, m = bm & 1023;
    const int co = threadIdx.x;
    const float2 af = g_aff[co];
    const float2 mm = g_mm[(size_t)bm*256 + co];
    const float v = (af.x >= 0.f) ? mm.x : mm.y;
    out[Bb*Mm*3 + (((size_t)(b*256 + co)) << 10) + m] = fmaxf(fmaf(af.x, v, af.y), 0.f);
}

// -------------------- launch ----------------------------------------------
#define SMEM_G1  75776                        // non-ARES (dbl A + dbl B)
#define SMEM_G23 (8192 + 4*16384 + 2*16384)   // ARES: 106496

extern "C" void kernel_launch(void* const* d_in, const int* in_sizes, int n_in,
                              void* d_out, int out_size)
{
    const float* points_xyz = (const float*)d_in[0];
    const float* features   = (const float*)d_in[1];
    const int*   indices    = (const int*)  d_in[2];
    const float* w1 = (const float*)d_in[3];
    const float* b1 = (const float*)d_in[4];
    const float* g1 = (const float*)d_in[5];
    const float* be1= (const float*)d_in[6];
    const float* w2 = (const float*)d_in[7];
    const float* b2 = (const float*)d_in[8];
    const float* g2 = (const float*)d_in[9];
    const float* be2= (const float*)d_in[10];
    const float* w3 = (const float*)d_in[11];
    const float* b3 = (const float*)d_in[12];
    const float* g3 = (const float*)d_in[13];
    const float* be3= (const float*)d_in[14];
    float* out = (float*)d_out;

    float *W1p, *Y1, *Y2;
    cudaGetSymbolAddress((void**)&W1p, g_W1p);
    cudaGetSymbolAddress((void**)&Y1,  g_Y1);
    cudaGetSymbolAddress((void**)&Y2,  g_Y2);

    cudaFuncSetAttribute(mma_gemm<XK,  5, 128, false, true,  false, false>, cudaFuncAttributeMaxDynamicSharedMemorySize, SMEM_G1);
    cudaFuncSetAttribute(mma_gemm<128, 4, 128, true,  false, false, true >, cudaFuncAttributeMaxDynamicSharedMemorySize, SMEM_G23);
    cudaFuncSetAttribute(mma_gemm<128, 4, 256, true,  false, true,  true >, cudaFuncAttributeMaxDynamicSharedMemorySize, SMEM_G23);

    // prep (2 launches)
    transpose_kernel<<<dim3(Nn/32, Cc/32, Bb), dim3(32,8)>>>(features);
    small_prep_kernel<<<(Bb*Nn + 255)/256, 256>>>(points_xyz, indices, w1, out);

    // ball query: 16 warps per query
    ballquery_kernel<<<Bb*Mm, 512>>>();

    // layer 1 (gather fused, non-resident A)
    mma_gemm<XK, 5, 128, false, true, false, false><<<dim3(NBLK, 1), 128, SMEM_G1>>>(W1p, nullptr, b1, Y1);
    finalize_kernel<<<128, 256>>>(g1, be1);

    // layer 2 (A-resident)
    mma_gemm<128, 4, 128, true, false, false, true><<<dim3(NBLK, 1), 128, SMEM_G23>>>(w2, Y1, b2, Y2);
    finalize_kernel<<<128, 256>>>(g2, be2);

    // layer 3 (A-resident, K-max/min fused)
    mma_gemm<128, 4, 256, true, false, true, true><<<dim3(NBLK, 2), 128, SMEM_G23>>>(w3, Y2, b3, nullptr);
    finalize_kernel<<<256, 256>>>(g3, be3);

    // final: affine + relu on reduced extrema
    finalmax_kernel<<<Bb*Mm, 256>>>(out);

    (void)in_sizes; (void)n_in; (void)out_size;
}